// round 5
// baseline (speedup 1.0000x reference)
#include <cuda_runtime.h>
#include <cstdint>
#include <math.h>

#define BATCH   4
#define SEQ     2048
#define DMODEL  1024
#define DINNER  2048
#define DSTATE  64
#define MROWS   (BATCH*SEQ)      /* 8192 */
#define NPROJ   (2*DSTATE+1)     /* 129  */
#define NCH     16               /* scan chunks */
#define CHLEN   (SEQ/NCH)        /* 128 */

// ---------------- scratch (device globals; no allocations allowed) ----------
__device__ float g_xi  [MROWS*DINNER];
__device__ float g_sz  [MROWS*DINNER];
__device__ float g_y   [MROWS*DINNER];
__device__ float g_pBC [MROWS*128];
__device__ float g_dsum[MROWS];
__device__ float g_a   [MROWS];
__device__ float g_hend [BATCH*NCH*DINNER];
__device__ float g_carry[BATCH*NCH*DINNER];
__device__ float g_prodA[BATCH*NCH];
__device__ float g_Wr  [DMODEL*2*DINNER];   // rounded W_in
__device__ float g_Wor [DINNER*DMODEL];     // rounded W_out

// ---------------- helpers ---------------------------------------------------
__device__ __forceinline__ uint32_t smem_u32(const void* p) {
    uint32_t a;
    asm("{ .reg .u64 t; cvta.to.shared.u64 t, %1; cvt.u32.u64 %0, t; }" : "=r"(a) : "l"(p));
    return a;
}
__device__ __forceinline__ float tf32r(float x) {
    float y; asm("cvt.rna.tf32.f32 %0, %1;" : "=f"(y) : "f"(x)); return y;
}
__device__ __forceinline__ void cp16(uint32_t s, const void* g) {
    asm volatile("cp.async.cg.shared.global [%0], [%1], 16;" :: "r"(s), "l"(g));
}
__device__ __forceinline__ void cp4(uint32_t s, const void* g) {
    asm volatile("cp.async.ca.shared.global [%0], [%1], 4;" :: "r"(s), "l"(g));
}
#define CP_COMMIT asm volatile("cp.async.commit_group;" ::: "memory")
#define CP_WAIT1  asm volatile("cp.async.wait_group 1;" ::: "memory")
#define CP_WAIT0  asm volatile("cp.async.wait_group 0;" ::: "memory")

__device__ __forceinline__ void mma8(float* c, const uint32_t* a, const uint32_t* b) {
    asm volatile(
        "mma.sync.aligned.m16n8k8.row.col.f32.tf32.tf32.f32 "
        "{%0,%1,%2,%3}, {%4,%5,%6,%7}, {%8,%9}, {%0,%1,%2,%3};"
        : "+f"(c[0]), "+f"(c[1]), "+f"(c[2]), "+f"(c[3])
        : "r"(a[0]), "r"(a[1]), "r"(a[2]), "r"(a[3]), "r"(b[0]), "r"(b[1]));
}

// ---------------- weight pre-round kernel -----------------------------------
__global__ __launch_bounds__(256)
void round_kernel(const float* __restrict__ src, float* __restrict__ dst, int n4)
{
    int i = blockIdx.x * 256 + threadIdx.x;
    if (i < n4) {
        float4 v = reinterpret_cast<const float4*>(src)[i];
        v.x = tf32r(v.x); v.y = tf32r(v.y); v.z = tf32r(v.z); v.w = tf32r(v.w);
        reinterpret_cast<float4*>(dst)[i] = v;
    }
}

// ======================= tf32 mma.sync GEMM, cp.async 3-stage ===============
// Block tile 128x128, BK=32, 256 thr.  Warp tile 32(M) x 64(N).
// MODE 0: C0=v   MODE 1: split xi / silu(z)   MODE 3: atomicAdd (split-K) + dsum
// BCVT: cvt B frags to tf32 at load (false when B pre-rounded)
#define STG_SZ  35840u     /* 18432 A + 17408 B per stage */
#define GEMM_SMEM  107520  /* 3 stages */
#define GEMM_SMEM3 109568  /* + 512-float w0 buffer */

template <int MODE, bool PRECISE, bool BALIGN, bool BCVT>
__global__ void __launch_bounds__(256, 2)
gemm_cp(const float* __restrict__ A, int lda,
        const float* __restrict__ B, int ldb,
        float* __restrict__ C0, float* __restrict__ C1,
        const float* __restrict__ wcol,
        int N, int K)
{
    extern __shared__ char smem[];
    const uint32_t sbase = smem_u32(smem);
    float* fs = (float*)smem;
    float* w0s = fs + GEMM_SMEM / 4;   // MODE 3 only

    const int t    = threadIdx.x;
    const int lane = t & 31;
    const int wid  = t >> 5;
    const int warpM = wid & 3;
    const int warpN = wid >> 2;
    const int rowBase = blockIdx.y * 128;
    const int colBase = blockIdx.x * 128;
    const int kBase   = blockIdx.z * K;

    float acc[2][8][4];
#pragma unroll
    for (int i = 0; i < 2; i++)
#pragma unroll
        for (int j = 0; j < 8; j++)
#pragma unroll
            for (int q = 0; q < 4; q++) acc[i][j][q] = 0.0f;

    const int nkt = K / 32;

    auto issue = [&](int st, int kt) {
        const int k0 = kBase + kt * 32;
        const uint32_t sA = sbase + st * STG_SZ;
        const uint32_t sB = sA + 18432u;
#pragma unroll
        for (int e = 0; e < 4; e++) {
            int id = t + 256 * e;
            int r = id >> 3, q = id & 7;
            cp16(sA + (uint32_t)(r * 36 + q * 4) * 4,
                 A + (size_t)(rowBase + r) * lda + k0 + q * 4);
        }
        if (BALIGN) {
#pragma unroll
            for (int e = 0; e < 4; e++) {
                int id = t + 256 * e;
                int k = id >> 5, q = id & 31;
                cp16(sB + (uint32_t)(k * 136 + q * 4) * 4,
                     B + (size_t)(k0 + k) * ldb + colBase + q * 4);
            }
        } else {
#pragma unroll
            for (int e = 0; e < 16; e++) {
                int id = t + 256 * e;
                int k = id >> 7, n = id & 127;
                cp4(sB + (uint32_t)(k * 136 + n) * 4,
                    B + (size_t)(k0 + k) * ldb + colBase + n);
            }
        }
    };

    issue(0, 0);
    CP_COMMIT;
    if (nkt > 1) { issue(1, 1); CP_COMMIT; }

    if (MODE == 3) {
        for (int i = t; i < K; i += 256)
            w0s[i] = wcol[(size_t)(kBase + i) * NPROJ];
    }
    float ds = 0.0f;

    const int r0 = warpM * 32 + (lane >> 2);
    const int kq = lane & 3;
    const int cl = warpN * 64 + (lane >> 2);

    for (int kt = 0; kt < nkt; kt++) {
        if (kt < nkt - 1) CP_WAIT1; else CP_WAIT0;
        __syncthreads();
        if (kt + 2 < nkt) { issue((kt + 2) % 3, kt + 2); CP_COMMIT; }

        const uint32_t aS = (uint32_t)(kt % 3) * (STG_SZ / 4);
        const uint32_t bS = aS + 18432 / 4;
#pragma unroll
        for (int ks = 0; ks < 4; ks++) {
            const int kb = ks * 8;
            uint32_t af[2][4], afl[2][4];
#pragma unroll
            for (int mt = 0; mt < 2; mt++) {
                int rr = r0 + mt * 16;
                float a0 = fs[aS + (rr    ) * 36 + kb + kq];
                float a1 = fs[aS + (rr + 8) * 36 + kb + kq];
                float a2 = fs[aS + (rr    ) * 36 + kb + kq + 4];
                float a3 = fs[aS + (rr + 8) * 36 + kb + kq + 4];
                float h0 = tf32r(a0), h1 = tf32r(a1), h2 = tf32r(a2), h3 = tf32r(a3);
                af[mt][0] = __float_as_uint(h0); af[mt][1] = __float_as_uint(h1);
                af[mt][2] = __float_as_uint(h2); af[mt][3] = __float_as_uint(h3);
                if (PRECISE) {
                    afl[mt][0] = __float_as_uint(tf32r(a0 - h0));
                    afl[mt][1] = __float_as_uint(tf32r(a1 - h1));
                    afl[mt][2] = __float_as_uint(tf32r(a2 - h2));
                    afl[mt][3] = __float_as_uint(tf32r(a3 - h3));
                }
            }
#pragma unroll
            for (int nt = 0; nt < 8; nt++) {
                int cc = cl + nt * 8;
                float b0 = fs[bS + (kb + kq    ) * 136 + cc];
                float b1 = fs[bS + (kb + kq + 4) * 136 + cc];
                if (PRECISE) {
                    float g0 = tf32r(b0), g1 = tf32r(b1);
                    uint32_t bf[2]  = { __float_as_uint(g0), __float_as_uint(g1) };
                    uint32_t bfl[2] = { __float_as_uint(tf32r(b0 - g0)),
                                        __float_as_uint(tf32r(b1 - g1)) };
#pragma unroll
                    for (int mt = 0; mt < 2; mt++) {
                        mma8(acc[mt][nt], af[mt],  bfl);
                        mma8(acc[mt][nt], afl[mt], bf);
                        mma8(acc[mt][nt], af[mt],  bf);
                    }
                } else {
                    if (BCVT) { b0 = tf32r(b0); b1 = tf32r(b1); }
                    uint32_t bf[2] = { __float_as_uint(b0), __float_as_uint(b1) };
#pragma unroll
                    for (int mt = 0; mt < 2; mt++)
                        mma8(acc[mt][nt], af[mt], bf);
                }
            }
        }
        if (MODE == 3) {
            int row = t & 127, kh = (t >> 7) * 16;
#pragma unroll
            for (int j = 0; j < 16; j++)
                ds += fs[aS + row * 36 + kh + j] * w0s[kt * 32 + kh + j];
        }
    }

    // ---- epilogue
    float* C = C0;
    int cbase = colBase;
    bool do_silu = false;
    int cstride = N;
    if (MODE == 1) {
        cstride = DINNER;
        if (colBase >= DINNER) { C = C1; cbase = colBase - DINNER; do_silu = true; }
    }

#pragma unroll
    for (int mt = 0; mt < 2; mt++) {
#pragma unroll
        for (int nt = 0; nt < 8; nt++) {
            int gr = rowBase + warpM * 32 + mt * 16 + (lane >> 2);
            int gc = cbase + warpN * 64 + nt * 8 + 2 * (lane & 3);
#pragma unroll
            for (int h = 0; h < 2; h++) {
                float v0 = acc[mt][nt][2 * h];
                float v1 = acc[mt][nt][2 * h + 1];
                int r = gr + h * 8;
                if (MODE == 1 && do_silu) {
                    v0 = v0 / (1.0f + expf(-v0));
                    v1 = v1 / (1.0f + expf(-v1));
                }
                if (MODE == 3) {
                    atomicAdd(C + (size_t)r * cstride + gc,     v0);
                    atomicAdd(C + (size_t)r * cstride + gc + 1, v1);
                } else {
                    float2 o; o.x = v0; o.y = v1;
                    *reinterpret_cast<float2*>(C + (size_t)r * cstride + gc) = o;
                }
            }
        }
    }

    if (MODE == 3) {
        __syncthreads();
        w0s[t] = ds;
        __syncthreads();
        if (t < 128)
            atomicAdd(&g_dsum[rowBase + t], w0s[t] + w0s[t + 128]);
    }
}

// ---------------- softplus -> A_bar -----------------------------------------
__global__ __launch_bounds__(256)
void softplus_kernel(const float* __restrict__ A_log)
{
    int m = blockIdx.x * 256 + threadIdx.x;
    float v = g_dsum[m];
    float sp = (v > 20.0f) ? v : log1pf(expf(v));
    g_a[m] = expf(-expf(A_log[0]) * sp);
}

// ---------------- fusedA: B-tile mma + local scan -> hend -------------------
// grid (64 bc, 16 dblk), 256 threads, occ 1
#define FA_CHUNK 0          /* [128][68]  floats */
#define FA_W     8704       /* [64][136]  floats (float offset) */
#define FA_STAGE 17408      /* [128][132] floats */
#define FA_AVEC  34304      /* [128] */
#define FA_SMEM  137728     /* bytes */

__global__ __launch_bounds__(256, 1)
void fusedA_kernel(const float* __restrict__ WB)
{
    extern __shared__ char sm[];
    float* fs = (float*)sm;
    const int t = threadIdx.x, lane = t & 31, w = t >> 5;
    const int bc = blockIdx.x, d0 = blockIdx.y * 128;
    const int row0 = bc * 128;

#pragma unroll
    for (int e = 0; e < 8; e++) {          // B_raw chunk [128][64]
        int id = t + 256 * e;
        int r = id >> 4, q = id & 15;
        float4 v = *reinterpret_cast<const float4*>(&g_pBC[(size_t)(row0 + r) * 128 + q * 4]);
        *reinterpret_cast<float4*>(&fs[FA_CHUNK + r * 68 + q * 4]) = v;
    }
#pragma unroll
    for (int e = 0; e < 8; e++) {          // W_B tile [64][128]
        int id = t + 256 * e;
        int k = id >> 5, q = id & 31;
        float4 v = *reinterpret_cast<const float4*>(&WB[(size_t)k * DINNER + d0 + q * 4]);
        *reinterpret_cast<float4*>(&fs[FA_W + k * 136 + q * 4]) = v;
    }
    if (t < 128) fs[FA_AVEC + t] = g_a[row0 + t];
    __syncthreads();

    float acc[16][4];
#pragma unroll
    for (int i = 0; i < 16; i++)
#pragma unroll
        for (int q = 0; q < 4; q++) acc[i][q] = 0.0f;

    const int r0 = w * 16 + (lane >> 2);
    const int kq = lane & 3;
    const int g  = lane >> 2;
#pragma unroll
    for (int ks = 0; ks < 8; ks++) {
        int kb = ks * 8;
        float a0 = fs[FA_CHUNK + r0 * 68 + kb + kq];
        float a1 = fs[FA_CHUNK + (r0 + 8) * 68 + kb + kq];
        float a2 = fs[FA_CHUNK + r0 * 68 + kb + kq + 4];
        float a3 = fs[FA_CHUNK + (r0 + 8) * 68 + kb + kq + 4];
        float h0 = tf32r(a0), h1 = tf32r(a1), h2 = tf32r(a2), h3 = tf32r(a3);
        uint32_t af[4]  = { __float_as_uint(h0), __float_as_uint(h1),
                            __float_as_uint(h2), __float_as_uint(h3) };
        uint32_t afl[4] = { __float_as_uint(tf32r(a0 - h0)), __float_as_uint(tf32r(a1 - h1)),
                            __float_as_uint(tf32r(a2 - h2)), __float_as_uint(tf32r(a3 - h3)) };
#pragma unroll
        for (int nt = 0; nt < 16; nt++) {
            int cc = nt * 8 + g;
            float b0 = fs[FA_W + (kb + kq) * 136 + cc];
            float b1 = fs[FA_W + (kb + kq + 4) * 136 + cc];
            float g0 = tf32r(b0), g1 = tf32r(b1);
            uint32_t bf[2]  = { __float_as_uint(g0), __float_as_uint(g1) };
            uint32_t bfl[2] = { __float_as_uint(tf32r(b0 - g0)), __float_as_uint(tf32r(b1 - g1)) };
            mma8(acc[nt], af,  bfl);
            mma8(acc[nt], afl, bf);
            mma8(acc[nt], af,  bf);
        }
    }
    // stage to [s][132]
#pragma unroll
    for (int nt = 0; nt < 16; nt++) {
        int c = nt * 8 + 2 * (lane & 3);
        int r = w * 16 + (lane >> 2);
        float2 lo; lo.x = acc[nt][0]; lo.y = acc[nt][1];
        float2 hi; hi.x = acc[nt][2]; hi.y = acc[nt][3];
        *reinterpret_cast<float2*>(&fs[FA_STAGE + r * 132 + c]) = lo;
        *reinterpret_cast<float2*>(&fs[FA_STAGE + (r + 8) * 132 + c]) = hi;
    }
    __syncthreads();

    if (t < 128) {
        float h = 0.0f;
        const float* xip = g_xi + (size_t)row0 * DINNER + d0 + t;
#pragma unroll 4
        for (int s = 0; s < 128; s++)
            h = fmaf(fs[FA_AVEC + s], h, fs[FA_STAGE + s * 132 + t] * xip[(size_t)s * DINNER]);
        g_hend[(size_t)bc * DINNER + d0 + t] = h;
    }
}

// ---------------- fusedB: B mma + scan(h) + C mma + fused epilogue ----------
#define FB_CHUNK 0          /* [128][132] floats */
#define FB_W     16896      /* [64][136]  floats */
#define FB_STAGE 25600      /* [128][132] floats */
#define FB_AVEC  42496      /* [128] */
#define FB_SMEM  170496     /* bytes */

__global__ __launch_bounds__(256, 1)
void fusedB_kernel(const float* __restrict__ WB, const float* __restrict__ WC,
                   const float* __restrict__ Dv)
{
    extern __shared__ char sm[];
    float* fs = (float*)sm;
    const int t = threadIdx.x, lane = t & 31, w = t >> 5;
    const int bc = blockIdx.x, d0 = blockIdx.y * 128;
    const int row0 = bc * 128;

#pragma unroll
    for (int e = 0; e < 16; e++) {         // full pBC chunk [128][128]
        int id = t + 256 * e;
        int r = id >> 5, q = id & 31;
        float4 v = *reinterpret_cast<const float4*>(&g_pBC[(size_t)(row0 + r) * 128 + q * 4]);
        *reinterpret_cast<float4*>(&fs[FB_CHUNK + r * 132 + q * 4]) = v;
    }
#pragma unroll
    for (int e = 0; e < 8; e++) {          // W_B tile
        int id = t + 256 * e;
        int k = id >> 5, q = id & 31;
        float4 v = *reinterpret_cast<const float4*>(&WB[(size_t)k * DINNER + d0 + q * 4]);
        *reinterpret_cast<float4*>(&fs[FB_W + k * 136 + q * 4]) = v;
    }
    if (t < 128) fs[FB_AVEC + t] = g_a[row0 + t];
    __syncthreads();

    float acc[16][4];
    const int r0 = w * 16 + (lane >> 2);
    const int kq = lane & 3;
    const int g  = lane >> 2;

    // ---- phase 1: B tile mma (chunk cols 0..63)
#pragma unroll
    for (int i = 0; i < 16; i++)
#pragma unroll
        for (int q = 0; q < 4; q++) acc[i][q] = 0.0f;
#pragma unroll
    for (int ks = 0; ks < 8; ks++) {
        int kb = ks * 8;
        float a0 = fs[FB_CHUNK + r0 * 132 + kb + kq];
        float a1 = fs[FB_CHUNK + (r0 + 8) * 132 + kb + kq];
        float a2 = fs[FB_CHUNK + r0 * 132 + kb + kq + 4];
        float a3 = fs[FB_CHUNK + (r0 + 8) * 132 + kb + kq + 4];
        float h0 = tf32r(a0), h1 = tf32r(a1), h2 = tf32r(a2), h3 = tf32r(a3);
        uint32_t af[4]  = { __float_as_uint(h0), __float_as_uint(h1),
                            __float_as_uint(h2), __float_as_uint(h3) };
        uint32_t afl[4] = { __float_as_uint(tf32r(a0 - h0)), __float_as_uint(tf32r(a1 - h1)),
                            __float_as_uint(tf32r(a2 - h2)), __float_as_uint(tf32r(a3 - h3)) };
#pragma unroll
        for (int nt = 0; nt < 16; nt++) {
            int cc = nt * 8 + g;
            float b0 = fs[FB_W + (kb + kq) * 136 + cc];
            float b1 = fs[FB_W + (kb + kq + 4) * 136 + cc];
            float g0 = tf32r(b0), g1 = tf32r(b1);
            uint32_t bf[2]  = { __float_as_uint(g0), __float_as_uint(g1) };
            uint32_t bfl[2] = { __float_as_uint(tf32r(b0 - g0)), __float_as_uint(tf32r(b1 - g1)) };
            mma8(acc[nt], af,  bfl);
            mma8(acc[nt], afl, bf);
            mma8(acc[nt], af,  bf);
        }
    }
#pragma unroll
    for (int nt = 0; nt < 16; nt++) {
        int c = nt * 8 + 2 * (lane & 3);
        int r = w * 16 + (lane >> 2);
        float2 lo; lo.x = acc[nt][0]; lo.y = acc[nt][1];
        float2 hi; hi.x = acc[nt][2]; hi.y = acc[nt][3];
        *reinterpret_cast<float2*>(&fs[FB_STAGE + r * 132 + c]) = lo;
        *reinterpret_cast<float2*>(&fs[FB_STAGE + (r + 8) * 132 + c]) = hi;
    }
    __syncthreads();

    // ---- phase 2: load W_C (all threads) + scan (t<128), overlapped
#pragma unroll
    for (int e = 0; e < 8; e++) {
        int id = t + 256 * e;
        int k = id >> 5, q = id & 31;
        float4 v = *reinterpret_cast<const float4*>(&WC[(size_t)k * DINNER + d0 + q * 4]);
        *reinterpret_cast<float4*>(&fs[FB_W + k * 136 + q * 4]) = v;
    }
    if (t < 128) {
        float h = g_carry[(size_t)bc * DINNER + d0 + t];
        const float* xip = g_xi + (size_t)row0 * DINNER + d0 + t;
#pragma unroll 4
        for (int s = 0; s < 128; s++) {
            h = fmaf(fs[FB_AVEC + s], h, fs[FB_STAGE + s * 132 + t] * xip[(size_t)s * DINNER]);
            fs[FB_STAGE + s * 132 + t] = h;
        }
    }
    __syncthreads();

    // ---- phase 3: C tile mma (chunk cols 64..127)
#pragma unroll
    for (int i = 0; i < 16; i++)
#pragma unroll
        for (int q = 0; q < 4; q++) acc[i][q] = 0.0f;
#pragma unroll
    for (int ks = 0; ks < 8; ks++) {
        int kb = ks * 8 + 64;
        float a0 = fs[FB_CHUNK + r0 * 132 + kb + kq];
        float a1 = fs[FB_CHUNK + (r0 + 8) * 132 + kb + kq];
        float a2 = fs[FB_CHUNK + r0 * 132 + kb + kq + 4];
        float a3 = fs[FB_CHUNK + (r0 + 8) * 132 + kb + kq + 4];
        float h0 = tf32r(a0), h1 = tf32r(a1), h2 = tf32r(a2), h3 = tf32r(a3);
        uint32_t af[4]  = { __float_as_uint(h0), __float_as_uint(h1),
                            __float_as_uint(h2), __float_as_uint(h3) };
        uint32_t afl[4] = { __float_as_uint(tf32r(a0 - h0)), __float_as_uint(tf32r(a1 - h1)),
                            __float_as_uint(tf32r(a2 - h2)), __float_as_uint(tf32r(a3 - h3)) };
        int kw = ks * 8;
#pragma unroll
        for (int nt = 0; nt < 16; nt++) {
            int cc = nt * 8 + g;
            float b0 = fs[FB_W + (kw + kq) * 136 + cc];
            float b1 = fs[FB_W + (kw + kq + 4) * 136 + cc];
            float g0 = tf32r(b0), g1 = tf32r(b1);
            uint32_t bf[2]  = { __float_as_uint(g0), __float_as_uint(g1) };
            uint32_t bfl[2] = { __float_as_uint(tf32r(b0 - g0)), __float_as_uint(tf32r(b1 - g1)) };
            mma8(acc[nt], af,  bfl);
            mma8(acc[nt], afl, bf);
            mma8(acc[nt], af,  bf);
        }
    }

    // ---- phase 4: y = (C*h + D*xi) * sz
#pragma unroll
    for (int nt = 0; nt < 16; nt++) {
        int c = nt * 8 + 2 * (lane & 3);
        float2 D2 = *reinterpret_cast<const float2*>(&Dv[d0 + c]);
#pragma unroll
        for (int h2 = 0; h2 < 2; h2++) {
            int rr = w * 16 + (lane >> 2) + 8 * h2;
            float hv0 = fs[FB_STAGE + rr * 132 + c];
            float hv1 = fs[FB_STAGE + rr * 132 + c + 1];
            size_t gidx = (size_t)(row0 + rr) * DINNER + d0 + c;
            float2 xiv = *reinterpret_cast<const float2*>(&g_xi[gidx]);
            float2 szv = *reinterpret_cast<const float2*>(&g_sz[gidx]);
            float y0 = fmaf(acc[nt][2 * h2],     hv0, D2.x * xiv.x) * szv.x;
            float y1 = fmaf(acc[nt][2 * h2 + 1], hv1, D2.y * xiv.y) * szv.y;
            float2 o; o.x = y0; o.y = y1;
            *reinterpret_cast<float2*>(&g_y[gidx]) = o;
        }
    }
}

// ---------------- chunk product of a ----------------------------------------
__global__ __launch_bounds__(128)
void prod_kernel()
{
    float v = g_a[blockIdx.x * 128 + threadIdx.x];
#pragma unroll
    for (int o = 16; o; o >>= 1) v *= __shfl_xor_sync(0xFFFFFFFFu, v, o);
    __shared__ float red[4];
    if ((threadIdx.x & 31) == 0) red[threadIdx.x >> 5] = v;
    __syncthreads();
    if (threadIdx.x == 0)
        g_prodA[blockIdx.x] = red[0] * red[1] * red[2] * red[3];
}

// ---------------- carries across chunks -------------------------------------
__global__ __launch_bounds__(256)
void carry_kernel()
{
    int b = blockIdx.x >> 3;
    int d = (blockIdx.x & 7) * 256 + threadIdx.x;
    float carry = 0.0f;
#pragma unroll
    for (int c = 0; c < NCH; c++) {
        size_t idx = (size_t)(b * NCH + c) * DINNER + d;
        g_carry[idx] = carry;
        carry = g_hend[idx] + g_prodA[b * NCH + c] * carry;
    }
}

// ---------------- launch ----------------------------------------------------
extern "C" void kernel_launch(void* const* d_in, const int* in_sizes, int n_in,
                              void* d_out, int out_size)
{
    const float* x     = (const float*)d_in[0];
    const float* W_in  = (const float*)d_in[1];
    const float* W_xp  = (const float*)d_in[2];
    const float* W_B   = (const float*)d_in[3];
    const float* W_C   = (const float*)d_in[4];
    const float* W_out = (const float*)d_in[5];
    const float* Dvec  = (const float*)d_in[6];
    const float* A_log = (const float*)d_in[7];
    float* out = (float*)d_out;

    float *p_xi, *p_sz, *p_y, *p_pBC, *p_dsum, *p_Wr, *p_Wor;
    cudaGetSymbolAddress((void**)&p_xi,   g_xi);
    cudaGetSymbolAddress((void**)&p_sz,   g_sz);
    cudaGetSymbolAddress((void**)&p_y,    g_y);
    cudaGetSymbolAddress((void**)&p_pBC,  g_pBC);
    cudaGetSymbolAddress((void**)&p_dsum, g_dsum);
    cudaGetSymbolAddress((void**)&p_Wr,   g_Wr);
    cudaGetSymbolAddress((void**)&p_Wor,  g_Wor);

    cudaFuncSetAttribute(gemm_cp<1,false,true,false>, cudaFuncAttributeMaxDynamicSharedMemorySize, GEMM_SMEM);
    cudaFuncSetAttribute(gemm_cp<0,false,true,false>, cudaFuncAttributeMaxDynamicSharedMemorySize, GEMM_SMEM);
    cudaFuncSetAttribute(gemm_cp<3,true,false,true>,  cudaFuncAttributeMaxDynamicSharedMemorySize, GEMM_SMEM3);
    cudaFuncSetAttribute(fusedA_kernel, cudaFuncAttributeMaxDynamicSharedMemorySize, FA_SMEM);
    cudaFuncSetAttribute(fusedB_kernel, cudaFuncAttributeMaxDynamicSharedMemorySize, FB_SMEM);

    // 0) pre-round weights; zero accumulators
    round_kernel<<<(DMODEL * 2 * DINNER / 4 + 255) / 256, 256>>>(W_in,  p_Wr,  DMODEL * 2 * DINNER / 4);
    round_kernel<<<(DINNER * DMODEL / 4 + 255) / 256, 256>>>(W_out, p_Wor, DINNER * DMODEL / 4);
    cudaMemsetAsync(p_pBC,  0, (size_t)MROWS * 128 * sizeof(float), 0);
    cudaMemsetAsync(p_dsum, 0, (size_t)MROWS * sizeof(float), 0);

    // 1) xz = x @ W_in, fused split -> xi, silu(z)
    gemm_cp<1,false,true,false><<<dim3(32, 64), 256, GEMM_SMEM>>>(
        x, DMODEL, p_Wr, 2 * DINNER, p_xi, p_sz, nullptr, 2 * DINNER, DMODEL);

    // 2) [B_raw|C_raw] = xi @ W_xp[:,1:129] (split-K x4, 3xtf32) + fused delta dot
    gemm_cp<3,true,false,true><<<dim3(1, 64, 4), 256, GEMM_SMEM3>>>(
        p_xi, DINNER, W_xp + 1, NPROJ, p_pBC, nullptr, W_xp, 128, DINNER / 4);

    // 3) softplus -> A_bar
    softplus_kernel<<<MROWS / 256, 256>>>(A_log);

    // 4) fused scan chain
    fusedA_kernel<<<dim3(BATCH * NCH, DINNER / 128), 256, FA_SMEM>>>(W_B);
    prod_kernel<<<BATCH * NCH, 128>>>();
    carry_kernel<<<BATCH * (DINNER / 256), 256>>>();
    fusedB_kernel<<<dim3(BATCH * NCH, DINNER / 128), 256, FB_SMEM>>>(W_B, W_C, Dvec);

    // 5) out = y @ W_out
    gemm_cp<0,false,true,false><<<dim3(8, 64), 256, GEMM_SMEM>>>(
        p_y, DINNER, p_Wor, DMODEL, out, nullptr, nullptr, DMODEL, DINNER);
}

// round 6
// speedup vs baseline: 1.7163x; 1.7163x over previous
#include <cuda_runtime.h>
#include <cstdint>
#include <math.h>

#define BATCH   4
#define SEQ     2048
#define DMODEL  1024
#define DINNER  2048
#define DSTATE  64
#define MROWS   (BATCH*SEQ)      /* 8192 */
#define NPROJ   (2*DSTATE+1)     /* 129  */
#define NCH     16               /* scan chunks */
#define CHLEN   (SEQ/NCH)        /* 128 */

// ---------------- scratch (device globals; no allocations allowed) ----------
__device__ float g_xi  [MROWS*DINNER];
__device__ float g_sz  [MROWS*DINNER];
__device__ float g_bx  [MROWS*DINNER];
__device__ float g_Cm  [MROWS*DINNER];
__device__ float g_y   [MROWS*DINNER];
__device__ float g_pBC [MROWS*128];
__device__ float g_a   [MROWS];
__device__ float g_hend [BATCH*NCH*DINNER];
__device__ float g_carry[BATCH*NCH*DINNER];
__device__ float g_prodA[BATCH*NCH];
__device__ float g_Wr  [DMODEL*2*DINNER];   // rounded W_in
__device__ float g_Wor [DINNER*DMODEL];     // rounded W_out
__device__ float g_Wxh [DINNER*128];        // W_xp[:,1:129] hi
__device__ float g_Wxl [DINNER*128];        // W_xp[:,1:129] lo
__device__ float g_WBh [DSTATE*DINNER];
__device__ float g_WBl [DSTATE*DINNER];
__device__ float g_WCh [DSTATE*DINNER];
__device__ float g_WCl [DSTATE*DINNER];

// ---------------- helpers ---------------------------------------------------
__device__ __forceinline__ uint32_t smem_u32(const void* p) {
    uint32_t a;
    asm("{ .reg .u64 t; cvta.to.shared.u64 t, %1; cvt.u32.u64 %0, t; }" : "=r"(a) : "l"(p));
    return a;
}
__device__ __forceinline__ float tf32r(float x) {
    float y; asm("cvt.rna.tf32.f32 %0, %1;" : "=f"(y) : "f"(x)); return y;
}
__device__ __forceinline__ void cp16(uint32_t s, const void* g) {
    asm volatile("cp.async.cg.shared.global [%0], [%1], 16;" :: "r"(s), "l"(g));
}
#define CP_COMMIT asm volatile("cp.async.commit_group;" ::: "memory")
#define CP_WAIT1  asm volatile("cp.async.wait_group 1;" ::: "memory")
#define CP_WAIT0  asm volatile("cp.async.wait_group 0;" ::: "memory")

__device__ __forceinline__ void mma8(float* c, const uint32_t* a, const uint32_t* b) {
    asm volatile(
        "mma.sync.aligned.m16n8k8.row.col.f32.tf32.tf32.f32 "
        "{%0,%1,%2,%3}, {%4,%5,%6,%7}, {%8,%9}, {%0,%1,%2,%3};"
        : "+f"(c[0]), "+f"(c[1]), "+f"(c[2]), "+f"(c[3])
        : "r"(a[0]), "r"(a[1]), "r"(a[2]), "r"(a[3]), "r"(b[0]), "r"(b[1]));
}

// ---------------- prep kernels ----------------------------------------------
__global__ __launch_bounds__(256)
void round_kernel(const float* __restrict__ src, float* __restrict__ dst, int n4)
{
    int i = blockIdx.x * 256 + threadIdx.x;
    if (i < n4) {
        float4 v = reinterpret_cast<const float4*>(src)[i];
        v.x = tf32r(v.x); v.y = tf32r(v.y); v.z = tf32r(v.z); v.w = tf32r(v.w);
        reinterpret_cast<float4*>(dst)[i] = v;
    }
}

__global__ __launch_bounds__(256)
void split_kernel(const float* __restrict__ src, float* __restrict__ dh,
                  float* __restrict__ dl, int n)
{
    int i = blockIdx.x * 256 + threadIdx.x;
    if (i < n) {
        float v = src[i];
        float h = tf32r(v);
        dh[i] = h;
        dl[i] = tf32r(v - h);
    }
}

// W_xp[:,1:129] (ldb 129) -> padded [DINNER][128] hi/lo
__global__ __launch_bounds__(256)
void splitxp_kernel(const float* __restrict__ W)
{
    int i = blockIdx.x * 256 + threadIdx.x;   // DINNER*128
    int k = i >> 7, n = i & 127;
    float v = W[(size_t)k * NPROJ + 1 + n];
    float h = tf32r(v);
    g_Wxh[i] = h;
    g_Wxl[i] = tf32r(v - h);
}

// ======================= tf32 mma.sync GEMM, cp.async 2-stage ===============
// Pre-rounded B (no cvt on B frags). A frags cvt'd in-loop.
// Block tile 128x128, BK=32, 256 thr.  Warp tile 32(M) x 64(N).
// MODE 0: C0=v   MODE 1: split xi / silu(z)
#define STG_SZ  35840u     /* 18432 A + 17408 B per stage */
#define GEMM_SMEM 71680

template <int MODE>
__global__ void __launch_bounds__(256, 2)
gemm_cp(const float* __restrict__ A, int lda,
        const float* __restrict__ B, int ldb,
        float* __restrict__ C0, float* __restrict__ C1,
        int N, int K)
{
    extern __shared__ char smem[];
    const uint32_t sbase = smem_u32(smem);
    float* fs = (float*)smem;

    const int t    = threadIdx.x;
    const int lane = t & 31;
    const int wid  = t >> 5;
    const int warpM = wid & 3;
    const int warpN = wid >> 2;
    const int rowBase = blockIdx.y * 128;
    const int colBase = blockIdx.x * 128;

    float acc[2][8][4];
#pragma unroll
    for (int i = 0; i < 2; i++)
#pragma unroll
        for (int j = 0; j < 8; j++)
#pragma unroll
            for (int q = 0; q < 4; q++) acc[i][j][q] = 0.0f;

    const int nkt = K / 32;

    auto issue = [&](int st, int kt) {
        const int k0 = kt * 32;
        const uint32_t sA = sbase + st * STG_SZ;
        const uint32_t sB = sA + 18432u;
#pragma unroll
        for (int e = 0; e < 4; e++) {
            int id = t + 256 * e;
            int r = id >> 3, q = id & 7;
            cp16(sA + (uint32_t)(r * 36 + q * 4) * 4,
                 A + (size_t)(rowBase + r) * lda + k0 + q * 4);
        }
#pragma unroll
        for (int e = 0; e < 4; e++) {
            int id = t + 256 * e;
            int k = id >> 5, q = id & 31;
            cp16(sB + (uint32_t)(k * 136 + q * 4) * 4,
                 B + (size_t)(k0 + k) * ldb + colBase + q * 4);
        }
    };

    issue(0, 0);
    CP_COMMIT;

    const int r0 = warpM * 32 + (lane >> 2);
    const int kq = lane & 3;
    const int cl = warpN * 64 + (lane >> 2);

    for (int kt = 0; kt < nkt; kt++) {
        if (kt + 1 < nkt) { issue((kt + 1) & 1, kt + 1); CP_COMMIT; CP_WAIT1; }
        else              { CP_WAIT0; }
        __syncthreads();

        const uint32_t aS = (uint32_t)(kt & 1) * (STG_SZ / 4);
        const uint32_t bS = aS + 18432 / 4;
#pragma unroll
        for (int ks = 0; ks < 4; ks++) {
            const int kb = ks * 8;
            uint32_t af[2][4];
#pragma unroll
            for (int mt = 0; mt < 2; mt++) {
                int rr = r0 + mt * 16;
                af[mt][0] = __float_as_uint(tf32r(fs[aS + (rr    ) * 36 + kb + kq]));
                af[mt][1] = __float_as_uint(tf32r(fs[aS + (rr + 8) * 36 + kb + kq]));
                af[mt][2] = __float_as_uint(tf32r(fs[aS + (rr    ) * 36 + kb + kq + 4]));
                af[mt][3] = __float_as_uint(tf32r(fs[aS + (rr + 8) * 36 + kb + kq + 4]));
            }
#pragma unroll
            for (int nt = 0; nt < 8; nt++) {
                int cc = cl + nt * 8;
                uint32_t bf[2] = {
                    __float_as_uint(fs[bS + (kb + kq    ) * 136 + cc]),
                    __float_as_uint(fs[bS + (kb + kq + 4) * 136 + cc]) };
#pragma unroll
                for (int mt = 0; mt < 2; mt++)
                    mma8(acc[mt][nt], af[mt], bf);
            }
        }
        __syncthreads();
    }

    // ---- epilogue
    float* C = C0;
    int cbase = colBase;
    bool do_silu = false;
    int cstride = N;
    if (MODE == 1) {
        cstride = DINNER;
        if (colBase >= DINNER) { C = C1; cbase = colBase - DINNER; do_silu = true; }
    }

#pragma unroll
    for (int mt = 0; mt < 2; mt++) {
#pragma unroll
        for (int nt = 0; nt < 8; nt++) {
            int gr = rowBase + warpM * 32 + mt * 16 + (lane >> 2);
            int gc = cbase + warpN * 64 + nt * 8 + 2 * (lane & 3);
#pragma unroll
            for (int h = 0; h < 2; h++) {
                float v0 = acc[mt][nt][2 * h];
                float v1 = acc[mt][nt][2 * h + 1];
                int r = gr + h * 8;
                if (MODE == 1 && do_silu) {
                    v0 = v0 / (1.0f + expf(-v0));
                    v1 = v1 / (1.0f + expf(-v1));
                }
                float2 o; o.x = v0; o.y = v1;
                *reinterpret_cast<float2*>(C + (size_t)r * cstride + gc) = o;
            }
        }
    }
}

// ============ 3xtf32 GEMM with prebuilt hi/lo B, cp.async 2-stage ===========
// MODE 0: C0=v   MODE 2: C0=v*aux   MODE 3: atomicAdd(C0, v) (split-K)
#define PP_STG  53248u     /* 18432 A + 17408 Bh + 17408 Bl */
#define PP_SMEM 106496

template <int MODE>
__global__ void __launch_bounds__(256, 2)
gemm_pp(const float* __restrict__ A, int lda,
        const float* __restrict__ Bh, const float* __restrict__ Bl, int ldb,
        float* __restrict__ C0, const float* __restrict__ aux,
        int N, int K)
{
    extern __shared__ char smem[];
    const uint32_t sbase = smem_u32(smem);
    float* fs = (float*)smem;

    const int t    = threadIdx.x;
    const int lane = t & 31;
    const int wid  = t >> 5;
    const int warpM = wid & 3;
    const int warpN = wid >> 2;
    const int rowBase = blockIdx.y * 128;
    const int colBase = blockIdx.x * 128;
    const int kBase   = blockIdx.z * K;

    float acc[2][8][4];
#pragma unroll
    for (int i = 0; i < 2; i++)
#pragma unroll
        for (int j = 0; j < 8; j++)
#pragma unroll
            for (int q = 0; q < 4; q++) acc[i][j][q] = 0.0f;

    const int nkt = K / 32;

    auto issue = [&](int st, int kt) {
        const int k0 = kBase + kt * 32;
        const uint32_t sA  = sbase + st * PP_STG;
        const uint32_t sBh = sA + 18432u;
        const uint32_t sBl = sBh + 17408u;
#pragma unroll
        for (int e = 0; e < 4; e++) {
            int id = t + 256 * e;
            int r = id >> 3, q = id & 7;
            cp16(sA + (uint32_t)(r * 36 + q * 4) * 4,
                 A + (size_t)(rowBase + r) * lda + k0 + q * 4);
        }
#pragma unroll
        for (int e = 0; e < 4; e++) {
            int id = t + 256 * e;
            int k = id >> 5, q = id & 31;
            cp16(sBh + (uint32_t)(k * 136 + q * 4) * 4,
                 Bh + (size_t)(k0 + k) * ldb + colBase + q * 4);
            cp16(sBl + (uint32_t)(k * 136 + q * 4) * 4,
                 Bl + (size_t)(k0 + k) * ldb + colBase + q * 4);
        }
    };

    issue(0, 0);
    CP_COMMIT;

    const int r0 = warpM * 32 + (lane >> 2);
    const int kq = lane & 3;
    const int cl = warpN * 64 + (lane >> 2);

    for (int kt = 0; kt < nkt; kt++) {
        if (kt + 1 < nkt) { issue((kt + 1) & 1, kt + 1); CP_COMMIT; CP_WAIT1; }
        else              { CP_WAIT0; }
        __syncthreads();

        const uint32_t aS  = (uint32_t)(kt & 1) * (PP_STG / 4);
        const uint32_t bhS = aS + 18432 / 4;
        const uint32_t blS = bhS + 17408 / 4;
#pragma unroll
        for (int ks = 0; ks < 4; ks++) {
            const int kb = ks * 8;
            uint32_t af[2][4], afl[2][4];
#pragma unroll
            for (int mt = 0; mt < 2; mt++) {
                int rr = r0 + mt * 16;
                float a0 = fs[aS + (rr    ) * 36 + kb + kq];
                float a1 = fs[aS + (rr + 8) * 36 + kb + kq];
                float a2 = fs[aS + (rr    ) * 36 + kb + kq + 4];
                float a3 = fs[aS + (rr + 8) * 36 + kb + kq + 4];
                float h0 = tf32r(a0), h1 = tf32r(a1), h2 = tf32r(a2), h3 = tf32r(a3);
                af[mt][0] = __float_as_uint(h0); af[mt][1] = __float_as_uint(h1);
                af[mt][2] = __float_as_uint(h2); af[mt][3] = __float_as_uint(h3);
                afl[mt][0] = __float_as_uint(tf32r(a0 - h0));
                afl[mt][1] = __float_as_uint(tf32r(a1 - h1));
                afl[mt][2] = __float_as_uint(tf32r(a2 - h2));
                afl[mt][3] = __float_as_uint(tf32r(a3 - h3));
            }
#pragma unroll
            for (int nt = 0; nt < 8; nt++) {
                int cc = cl + nt * 8;
                uint32_t bf[2] = {
                    __float_as_uint(fs[bhS + (kb + kq    ) * 136 + cc]),
                    __float_as_uint(fs[bhS + (kb + kq + 4) * 136 + cc]) };
                uint32_t bfl[2] = {
                    __float_as_uint(fs[blS + (kb + kq    ) * 136 + cc]),
                    __float_as_uint(fs[blS + (kb + kq + 4) * 136 + cc]) };
#pragma unroll
                for (int mt = 0; mt < 2; mt++) {
                    mma8(acc[mt][nt], af[mt],  bfl);
                    mma8(acc[mt][nt], afl[mt], bf);
                    mma8(acc[mt][nt], af[mt],  bf);
                }
            }
        }
        __syncthreads();
    }

    // ---- epilogue
#pragma unroll
    for (int mt = 0; mt < 2; mt++) {
#pragma unroll
        for (int nt = 0; nt < 8; nt++) {
            int gr = rowBase + warpM * 32 + mt * 16 + (lane >> 2);
            int gc = colBase + warpN * 64 + nt * 8 + 2 * (lane & 3);
#pragma unroll
            for (int h = 0; h < 2; h++) {
                float v0 = acc[mt][nt][2 * h];
                float v1 = acc[mt][nt][2 * h + 1];
                int r = gr + h * 8;
                if (MODE == 2) {
                    float2 a2 = *reinterpret_cast<const float2*>(aux + (size_t)r * N + gc);
                    v0 *= a2.x; v1 *= a2.y;
                }
                if (MODE == 3) {
                    atomicAdd(C0 + (size_t)r * N + gc,     v0);
                    atomicAdd(C0 + (size_t)r * N + gc + 1, v1);
                } else {
                    float2 o; o.x = v0; o.y = v1;
                    *reinterpret_cast<float2*>(C0 + (size_t)r * N + gc) = o;
                }
            }
        }
    }
}

// ---------------- delta: softplus(xi . W_xp[:,0]) -> A_bar ------------------
__global__ __launch_bounds__(256)
void delta_kernel(const float* __restrict__ xi, const float* __restrict__ W,
                  const float* __restrict__ A_log, float* __restrict__ ga)
{
    int m = blockIdx.x;
    const float* row = xi + (size_t)m * DINNER;
    float s = 0.0f;
    for (int k = threadIdx.x; k < DINNER; k += 256)
        s += row[k] * W[(size_t)k * NPROJ];
#pragma unroll
    for (int o = 16; o; o >>= 1) s += __shfl_xor_sync(0xFFFFFFFFu, s, o);
    __shared__ float red[8];
    if ((threadIdx.x & 31) == 0) red[threadIdx.x >> 5] = s;
    __syncthreads();
    if (threadIdx.x == 0) {
        float v = 0.0f;
#pragma unroll
        for (int i = 0; i < 8; i++) v += red[i];
        float sp = (v > 20.0f) ? v : log1pf(expf(v));
        ga[m] = expf(-expf(A_log[0]) * sp);
    }
}

// ---------------- parallel scan: 3 passes -----------------------------------
__global__ __launch_bounds__(128)
void prod_kernel()
{
    float v = g_a[blockIdx.x * 128 + threadIdx.x];
#pragma unroll
    for (int o = 16; o; o >>= 1) v *= __shfl_xor_sync(0xFFFFFFFFu, v, o);
    __shared__ float red[4];
    if ((threadIdx.x & 31) == 0) red[threadIdx.x >> 5] = v;
    __syncthreads();
    if (threadIdx.x == 0)
        g_prodA[blockIdx.x] = red[0] * red[1] * red[2] * red[3];
}

__global__ __launch_bounds__(256)
void scanA_kernel()
{
    int b = blockIdx.x >> 4, c = blockIdx.x & 15;
    int d = blockIdx.y * 256 + threadIdx.x;
    int s0 = c * CHLEN;
    float h = 0.0f;
    size_t base = ((size_t)b * SEQ + s0) * DINNER + d;
    int arow = b * SEQ + s0;
#pragma unroll 4
    for (int i = 0; i < CHLEN; i++)
        h = fmaf(g_a[arow + i], h, g_bx[base + (size_t)i * DINNER]);
    g_hend[(size_t)(b * NCH + c) * DINNER + d] = h;
}

__global__ __launch_bounds__(256)
void scanB_kernel()
{
    int b = blockIdx.x >> 3;
    int d = (blockIdx.x & 7) * 256 + threadIdx.x;
    float carry = 0.0f;
#pragma unroll
    for (int c = 0; c < NCH; c++) {
        size_t idx = (size_t)(b * NCH + c) * DINNER + d;
        g_carry[idx] = carry;
        carry = g_hend[idx] + g_prodA[b * NCH + c] * carry;
    }
}

__global__ __launch_bounds__(256)
void scanC_kernel(const float* __restrict__ D)
{
    int b = blockIdx.x >> 4, c = blockIdx.x & 15;
    int d = blockIdx.y * 256 + threadIdx.x;
    int s0 = c * CHLEN;
    float Dd = D[d];
    float h = g_carry[(size_t)(b * NCH + c) * DINNER + d];
    size_t base = ((size_t)b * SEQ + s0) * DINNER + d;
    int arow = b * SEQ + s0;
#pragma unroll 4
    for (int i = 0; i < CHLEN; i++) {
        size_t idx = base + (size_t)i * DINNER;
        float xi = g_xi[idx];
        h = fmaf(g_a[arow + i], h, g_bx[idx]);
        float y = fmaf(g_Cm[idx], h, Dd * xi);
        g_y[idx] = y * g_sz[idx];
    }
}

// ---------------- launch ----------------------------------------------------
extern "C" void kernel_launch(void* const* d_in, const int* in_sizes, int n_in,
                              void* d_out, int out_size)
{
    const float* x     = (const float*)d_in[0];
    const float* W_in  = (const float*)d_in[1];
    const float* W_xp  = (const float*)d_in[2];
    const float* W_B   = (const float*)d_in[3];
    const float* W_C   = (const float*)d_in[4];
    const float* W_out = (const float*)d_in[5];
    const float* Dvec  = (const float*)d_in[6];
    const float* A_log = (const float*)d_in[7];
    float* out = (float*)d_out;

    float *p_xi, *p_sz, *p_bx, *p_Cm, *p_y, *p_pBC, *p_a;
    float *p_Wr, *p_Wor, *p_Wxh, *p_Wxl, *p_WBh, *p_WBl, *p_WCh, *p_WCl;
    cudaGetSymbolAddress((void**)&p_xi,  g_xi);
    cudaGetSymbolAddress((void**)&p_sz,  g_sz);
    cudaGetSymbolAddress((void**)&p_bx,  g_bx);
    cudaGetSymbolAddress((void**)&p_Cm,  g_Cm);
    cudaGetSymbolAddress((void**)&p_y,   g_y);
    cudaGetSymbolAddress((void**)&p_pBC, g_pBC);
    cudaGetSymbolAddress((void**)&p_a,   g_a);
    cudaGetSymbolAddress((void**)&p_Wr,  g_Wr);
    cudaGetSymbolAddress((void**)&p_Wor, g_Wor);
    cudaGetSymbolAddress((void**)&p_Wxh, g_Wxh);
    cudaGetSymbolAddress((void**)&p_Wxl, g_Wxl);
    cudaGetSymbolAddress((void**)&p_WBh, g_WBh);
    cudaGetSymbolAddress((void**)&p_WBl, g_WBl);
    cudaGetSymbolAddress((void**)&p_WCh, g_WCh);
    cudaGetSymbolAddress((void**)&p_WCl, g_WCl);

    cudaFuncSetAttribute(gemm_cp<0>, cudaFuncAttributeMaxDynamicSharedMemorySize, GEMM_SMEM);
    cudaFuncSetAttribute(gemm_cp<1>, cudaFuncAttributeMaxDynamicSharedMemorySize, GEMM_SMEM);
    cudaFuncSetAttribute(gemm_pp<0>, cudaFuncAttributeMaxDynamicSharedMemorySize, PP_SMEM);
    cudaFuncSetAttribute(gemm_pp<2>, cudaFuncAttributeMaxDynamicSharedMemorySize, PP_SMEM);
    cudaFuncSetAttribute(gemm_pp<3>, cudaFuncAttributeMaxDynamicSharedMemorySize, PP_SMEM);

    // 0) weight prep + zero accumulators
    round_kernel<<<DMODEL * 2 * DINNER / 1024, 256>>>(W_in,  p_Wr,  DMODEL * 2 * DINNER / 4);
    round_kernel<<<DINNER * DMODEL / 1024, 256>>>(W_out, p_Wor, DINNER * DMODEL / 4);
    split_kernel<<<DSTATE * DINNER / 256, 256>>>(W_B, p_WBh, p_WBl, DSTATE * DINNER);
    split_kernel<<<DSTATE * DINNER / 256, 256>>>(W_C, p_WCh, p_WCl, DSTATE * DINNER);
    splitxp_kernel<<<DINNER * 128 / 256, 256>>>(W_xp);
    cudaMemsetAsync(p_pBC, 0, (size_t)MROWS * 128 * sizeof(float), 0);

    // 1) xz = x @ W_in, fused split -> xi, silu(z)
    gemm_cp<1><<<dim3(32, 64), 256, GEMM_SMEM>>>(
        x, DMODEL, p_Wr, 2 * DINNER, p_xi, p_sz, 2 * DINNER, DMODEL);

    // 2) delta -> A_bar
    delta_kernel<<<MROWS, 256>>>(p_xi, W_xp, A_log, p_a);

    // 3) [B_raw|C_raw] = xi @ W_xp[:,1:129]  (split-K x8, 3xtf32 prebuilt)
    gemm_pp<3><<<dim3(1, 64, 8), 256, PP_SMEM>>>(
        p_xi, DINNER, p_Wxh, p_Wxl, 128, p_pBC, nullptr, 128, DINNER / 8);

    // 4) bx = (B_raw @ W_B) * xi    (3xtf32 prebuilt)
    gemm_pp<2><<<dim3(16, 64), 256, PP_SMEM>>>(
        p_pBC, 128, p_WBh, p_WBl, DINNER, p_bx, p_xi, DINNER, DSTATE);

    // 5) Cm = C_raw @ W_C           (3xtf32 prebuilt)
    gemm_pp<0><<<dim3(16, 64), 256, PP_SMEM>>>(
        p_pBC + 64, 128, p_WCh, p_WCl, DINNER, p_Cm, nullptr, DINNER, DSTATE);

    // 6) parallel scan
    prod_kernel<<<BATCH * NCH, 128>>>();
    scanA_kernel<<<dim3(BATCH * NCH, DINNER / 256), 256>>>();
    scanB_kernel<<<BATCH * (DINNER / 256), 256>>>();
    scanC_kernel<<<dim3(BATCH * NCH, DINNER / 256), 256>>>(Dvec);

    // 7) out = y @ W_out
    gemm_cp<0><<<dim3(8, 64), 256, GEMM_SMEM>>>(
        p_y, DINNER, p_Wor, DMODEL, out, nullptr, DMODEL, DINNER);
}

// round 7
// speedup vs baseline: 1.7661x; 1.0290x over previous
#include <cuda_runtime.h>
#include <cstdint>
#include <math.h>

#define BATCH   4
#define SEQ     2048
#define DMODEL  1024
#define DINNER  2048
#define DSTATE  64
#define MROWS   (BATCH*SEQ)      /* 8192 */
#define NPROJ   (2*DSTATE+1)     /* 129  */
#define NCH     16               /* scan chunks */
#define CHLEN   (SEQ/NCH)        /* 128 */

// ---------------- scratch (device globals; no allocations allowed) ----------
__device__ float g_xi  [MROWS*DINNER];
__device__ float g_sz  [MROWS*DINNER];
__device__ float g_bx  [MROWS*DINNER];
__device__ float g_Cm  [MROWS*DINNER];
__device__ float g_y   [MROWS*DINNER];
__device__ float g_pBC [MROWS*128];
__device__ float g_dsum[MROWS];
__device__ float g_a   [MROWS];
__device__ float g_hend [BATCH*NCH*DINNER];
__device__ float g_carry[BATCH*NCH*DINNER];
__device__ float g_prodA[BATCH*NCH];
__device__ float g_xr  [MROWS*DMODEL];      // rounded x
__device__ float g_Wr  [DMODEL*2*DINNER];   // rounded W_in
__device__ float g_Wor [DINNER*DMODEL];     // rounded W_out
__device__ float g_Wxh [DINNER*128];        // W_xp[:,1:129] hi
__device__ float g_Wxl [DINNER*128];        // W_xp[:,1:129] lo
__device__ float g_WBh [DSTATE*DINNER];
__device__ float g_WBl [DSTATE*DINNER];
__device__ float g_WCh [DSTATE*DINNER];
__device__ float g_WCl [DSTATE*DINNER];

// ---------------- helpers ---------------------------------------------------
__device__ __forceinline__ uint32_t smem_u32(const void* p) {
    uint32_t a;
    asm("{ .reg .u64 t; cvta.to.shared.u64 t, %1; cvt.u32.u64 %0, t; }" : "=r"(a) : "l"(p));
    return a;
}
__device__ __forceinline__ float tf32r(float x) {
    float y; asm("cvt.rna.tf32.f32 %0, %1;" : "=f"(y) : "f"(x)); return y;
}
__device__ __forceinline__ void cp16(uint32_t s, const void* g) {
    asm volatile("cp.async.cg.shared.global [%0], [%1], 16;" :: "r"(s), "l"(g));
}
#define CP_COMMIT asm volatile("cp.async.commit_group;" ::: "memory")
#define CP_WAIT1  asm volatile("cp.async.wait_group 1;" ::: "memory")
#define CP_WAIT0  asm volatile("cp.async.wait_group 0;" ::: "memory")

__device__ __forceinline__ void mma8(float* c, const uint32_t* a, const uint32_t* b) {
    asm volatile(
        "mma.sync.aligned.m16n8k8.row.col.f32.tf32.tf32.f32 "
        "{%0,%1,%2,%3}, {%4,%5,%6,%7}, {%8,%9}, {%0,%1,%2,%3};"
        : "+f"(c[0]), "+f"(c[1]), "+f"(c[2]), "+f"(c[3])
        : "r"(a[0]), "r"(a[1]), "r"(a[2]), "r"(a[3]), "r"(b[0]), "r"(b[1]));
}

// ---------------- prep kernels ----------------------------------------------
__global__ __launch_bounds__(256)
void round_kernel(const float* __restrict__ src, float* __restrict__ dst, int n4)
{
    int i = blockIdx.x * 256 + threadIdx.x;
    if (i < n4) {
        float4 v = reinterpret_cast<const float4*>(src)[i];
        v.x = tf32r(v.x); v.y = tf32r(v.y); v.z = tf32r(v.z); v.w = tf32r(v.w);
        reinterpret_cast<float4*>(dst)[i] = v;
    }
}

__global__ __launch_bounds__(256)
void split_kernel(const float* __restrict__ src, float* __restrict__ dh,
                  float* __restrict__ dl, int n)
{
    int i = blockIdx.x * 256 + threadIdx.x;
    if (i < n) {
        float v = src[i];
        float h = tf32r(v);
        dh[i] = h;
        dl[i] = tf32r(v - h);
    }
}

// W_xp[:,1:129] (ldb 129) -> padded [DINNER][128] hi/lo
__global__ __launch_bounds__(256)
void splitxp_kernel(const float* __restrict__ W)
{
    int i = blockIdx.x * 256 + threadIdx.x;   // DINNER*128
    int k = i >> 7, n = i & 127;
    float v = W[(size_t)k * NPROJ + 1 + n];
    float h = tf32r(v);
    g_Wxh[i] = h;
    g_Wxl[i] = tf32r(v - h);
}

// ======================= tf32 mma.sync GEMM, cp.async 3-stage ===============
// A and B both pre-rounded to tf32 (NO cvt in mainloop). Single sync per iter.
// Block tile 128x128, BK=32, 256 thr.  Warp tile 32(M) x 64(N).
// MODE 0: C0=v   MODE 1: split xi / silu(z), fused delta dot into g_dsum
#define STG_SZ  35840u     /* 18432 A + 17408 B per stage */
#define GEMM_SMEM 107520   /* 3 stages */

template <int MODE>
__global__ void __launch_bounds__(256, 2)
gemm_cp(const float* __restrict__ A, int lda,
        const float* __restrict__ B, int ldb,
        float* __restrict__ C0, float* __restrict__ C1,
        const float* __restrict__ wxp,
        int N, int K)
{
    extern __shared__ char smem[];
    const uint32_t sbase = smem_u32(smem);
    float* fs = (float*)smem;

    const int t    = threadIdx.x;
    const int lane = t & 31;
    const int wid  = t >> 5;
    const int warpM = wid & 3;
    const int warpN = wid >> 2;

    // CTA raster swizzle: panels of 8 row-bands share column sweeps (L2 reuse)
    int bx = blockIdx.x, by = blockIdx.y;
    {
        int lin = by * gridDim.x + bx;
        int per = gridDim.x * 8;
        int p = lin / per, rem = lin % per;
        by = p * 8 + (rem & 7);
        bx = rem >> 3;
    }
    const int rowBase = by * 128;
    const int colBase = bx * 128;

    float acc[2][8][4];
#pragma unroll
    for (int i = 0; i < 2; i++)
#pragma unroll
        for (int j = 0; j < 8; j++)
#pragma unroll
            for (int q = 0; q < 4; q++) acc[i][j][q] = 0.0f;

    const int nkt = K / 32;

    auto issue = [&](int st, int kt) {
        const int k0 = kt * 32;
        const uint32_t sA = sbase + (uint32_t)st * STG_SZ;
        const uint32_t sB = sA + 18432u;
#pragma unroll
        for (int e = 0; e < 4; e++) {
            int id = t + 256 * e;
            int r = id >> 3, q = id & 7;
            cp16(sA + (uint32_t)(r * 36 + q * 4) * 4,
                 A + (size_t)(rowBase + r) * lda + k0 + q * 4);
        }
#pragma unroll
        for (int e = 0; e < 4; e++) {
            int id = t + 256 * e;
            int k = id >> 5, q = id & 31;
            cp16(sB + (uint32_t)(k * 136 + q * 4) * 4,
                 B + (size_t)(k0 + k) * ldb + colBase + q * 4);
        }
    };

    issue(0, 0);
    CP_COMMIT;
    if (nkt > 1) { issue(1, 1); CP_COMMIT; }

    const int r0 = warpM * 32 + (lane >> 2);
    const int kq = lane & 3;
    const int cl = warpN * 64 + (lane >> 2);

    for (int kt = 0; kt < nkt; kt++) {
        if (kt + 1 < nkt) CP_WAIT1; else CP_WAIT0;
        __syncthreads();
        if (kt + 2 < nkt) { issue((kt + 2) % 3, kt + 2); CP_COMMIT; }

        const uint32_t aS = (uint32_t)(kt % 3) * (STG_SZ / 4);
        const uint32_t bS = aS + 18432 / 4;
#pragma unroll
        for (int ks = 0; ks < 4; ks++) {
            const int kb = ks * 8;
            uint32_t af[2][4];
#pragma unroll
            for (int mt = 0; mt < 2; mt++) {
                int rr = r0 + mt * 16;
                af[mt][0] = __float_as_uint(fs[aS + (rr    ) * 36 + kb + kq]);
                af[mt][1] = __float_as_uint(fs[aS + (rr + 8) * 36 + kb + kq]);
                af[mt][2] = __float_as_uint(fs[aS + (rr    ) * 36 + kb + kq + 4]);
                af[mt][3] = __float_as_uint(fs[aS + (rr + 8) * 36 + kb + kq + 4]);
            }
#pragma unroll
            for (int nt = 0; nt < 8; nt++) {
                int cc = cl + nt * 8;
                uint32_t bf[2] = {
                    __float_as_uint(fs[bS + (kb + kq    ) * 136 + cc]),
                    __float_as_uint(fs[bS + (kb + kq + 4) * 136 + cc]) };
#pragma unroll
                for (int mt = 0; mt < 2; mt++)
                    mma8(acc[mt][nt], af[mt], bf);
            }
        }
    }

    // ---- epilogue
    float* C = C0;
    int cbase = colBase;
    bool do_silu = false;
    int cstride = N;
    if (MODE == 1) {
        cstride = DINNER;
        if (colBase >= DINNER) { C = C1; cbase = colBase - DINNER; do_silu = true; }
    }

    float ds[4] = {0.0f, 0.0f, 0.0f, 0.0f};

#pragma unroll
    for (int mt = 0; mt < 2; mt++) {
#pragma unroll
        for (int nt = 0; nt < 8; nt++) {
            int gr = rowBase + warpM * 32 + mt * 16 + (lane >> 2);
            int gc = cbase + warpN * 64 + nt * 8 + 2 * (lane & 3);
            float w0a = 0.0f, w0b = 0.0f;
            if (MODE == 1 && !do_silu) {
                w0a = __ldg(&wxp[(size_t)gc * NPROJ]);
                w0b = __ldg(&wxp[(size_t)(gc + 1) * NPROJ]);
            }
#pragma unroll
            for (int h = 0; h < 2; h++) {
                float v0 = acc[mt][nt][2 * h];
                float v1 = acc[mt][nt][2 * h + 1];
                int r = gr + h * 8;
                if (MODE == 1) {
                    if (do_silu) {
                        v0 = v0 / (1.0f + expf(-v0));
                        v1 = v1 / (1.0f + expf(-v1));
                    } else {
                        ds[mt * 2 + h] += v0 * w0a + v1 * w0b;
                    }
                }
                float2 o; o.x = v0; o.y = v1;
                *reinterpret_cast<float2*>(C + (size_t)r * cstride + gc) = o;
            }
        }
    }

    if (MODE == 1 && !do_silu) {
#pragma unroll
        for (int i = 0; i < 4; i++) {
            float v = ds[i];
            v += __shfl_xor_sync(0xFFFFFFFFu, v, 1);
            v += __shfl_xor_sync(0xFFFFFFFFu, v, 2);
            if ((lane & 3) == 0) {
                int r = rowBase + warpM * 32 + (i >> 1) * 16 + (i & 1) * 8 + (lane >> 2);
                atomicAdd(&g_dsum[r], v);
            }
        }
    }
}

// ============ 3xtf32 GEMM with prebuilt hi/lo B, cp.async 2-stage ===========
// MODE 0: C0=v   MODE 2: C0=v*aux   MODE 3: atomicAdd(C0, v) (split-K)
#define PP_STG  53248u     /* 18432 A + 17408 Bh + 17408 Bl */
#define PP_SMEM 106496

template <int MODE>
__global__ void __launch_bounds__(256, 2)
gemm_pp(const float* __restrict__ A, int lda,
        const float* __restrict__ Bh, const float* __restrict__ Bl, int ldb,
        float* __restrict__ C0, const float* __restrict__ aux,
        int N, int K)
{
    extern __shared__ char smem[];
    const uint32_t sbase = smem_u32(smem);
    float* fs = (float*)smem;

    const int t    = threadIdx.x;
    const int lane = t & 31;
    const int wid  = t >> 5;
    const int warpM = wid & 3;
    const int warpN = wid >> 2;
    const int rowBase = blockIdx.y * 128;
    const int colBase = blockIdx.x * 128;
    const int kBase   = blockIdx.z * K;

    float acc[2][8][4];
#pragma unroll
    for (int i = 0; i < 2; i++)
#pragma unroll
        for (int j = 0; j < 8; j++)
#pragma unroll
            for (int q = 0; q < 4; q++) acc[i][j][q] = 0.0f;

    const int nkt = K / 32;

    auto issue = [&](int st, int kt) {
        const int k0 = kBase + kt * 32;
        const uint32_t sA  = sbase + st * PP_STG;
        const uint32_t sBh = sA + 18432u;
        const uint32_t sBl = sBh + 17408u;
#pragma unroll
        for (int e = 0; e < 4; e++) {
            int id = t + 256 * e;
            int r = id >> 3, q = id & 7;
            cp16(sA + (uint32_t)(r * 36 + q * 4) * 4,
                 A + (size_t)(rowBase + r) * lda + k0 + q * 4);
        }
#pragma unroll
        for (int e = 0; e < 4; e++) {
            int id = t + 256 * e;
            int k = id >> 5, q = id & 31;
            cp16(sBh + (uint32_t)(k * 136 + q * 4) * 4,
                 Bh + (size_t)(k0 + k) * ldb + colBase + q * 4);
            cp16(sBl + (uint32_t)(k * 136 + q * 4) * 4,
                 Bl + (size_t)(k0 + k) * ldb + colBase + q * 4);
        }
    };

    issue(0, 0);
    CP_COMMIT;

    const int r0 = warpM * 32 + (lane >> 2);
    const int kq = lane & 3;
    const int cl = warpN * 64 + (lane >> 2);

    for (int kt = 0; kt < nkt; kt++) {
        if (kt + 1 < nkt) { issue((kt + 1) & 1, kt + 1); CP_COMMIT; CP_WAIT1; }
        else              { CP_WAIT0; }
        __syncthreads();

        const uint32_t aS  = (uint32_t)(kt & 1) * (PP_STG / 4);
        const uint32_t bhS = aS + 18432 / 4;
        const uint32_t blS = bhS + 17408 / 4;
#pragma unroll
        for (int ks = 0; ks < 4; ks++) {
            const int kb = ks * 8;
            uint32_t af[2][4], afl[2][4];
#pragma unroll
            for (int mt = 0; mt < 2; mt++) {
                int rr = r0 + mt * 16;
                float a0 = fs[aS + (rr    ) * 36 + kb + kq];
                float a1 = fs[aS + (rr + 8) * 36 + kb + kq];
                float a2 = fs[aS + (rr    ) * 36 + kb + kq + 4];
                float a3 = fs[aS + (rr + 8) * 36 + kb + kq + 4];
                float h0 = tf32r(a0), h1 = tf32r(a1), h2 = tf32r(a2), h3 = tf32r(a3);
                af[mt][0] = __float_as_uint(h0); af[mt][1] = __float_as_uint(h1);
                af[mt][2] = __float_as_uint(h2); af[mt][3] = __float_as_uint(h3);
                afl[mt][0] = __float_as_uint(tf32r(a0 - h0));
                afl[mt][1] = __float_as_uint(tf32r(a1 - h1));
                afl[mt][2] = __float_as_uint(tf32r(a2 - h2));
                afl[mt][3] = __float_as_uint(tf32r(a3 - h3));
            }
#pragma unroll
            for (int nt = 0; nt < 8; nt++) {
                int cc = cl + nt * 8;
                uint32_t bf[2] = {
                    __float_as_uint(fs[bhS + (kb + kq    ) * 136 + cc]),
                    __float_as_uint(fs[bhS + (kb + kq + 4) * 136 + cc]) };
                uint32_t bfl[2] = {
                    __float_as_uint(fs[blS + (kb + kq    ) * 136 + cc]),
                    __float_as_uint(fs[blS + (kb + kq + 4) * 136 + cc]) };
#pragma unroll
                for (int mt = 0; mt < 2; mt++) {
                    mma8(acc[mt][nt], af[mt],  bfl);
                    mma8(acc[mt][nt], afl[mt], bf);
                    mma8(acc[mt][nt], af[mt],  bf);
                }
            }
        }
        __syncthreads();
    }

    // ---- epilogue
#pragma unroll
    for (int mt = 0; mt < 2; mt++) {
#pragma unroll
        for (int nt = 0; nt < 8; nt++) {
            int gr = rowBase + warpM * 32 + mt * 16 + (lane >> 2);
            int gc = colBase + warpN * 64 + nt * 8 + 2 * (lane & 3);
#pragma unroll
            for (int h = 0; h < 2; h++) {
                float v0 = acc[mt][nt][2 * h];
                float v1 = acc[mt][nt][2 * h + 1];
                int r = gr + h * 8;
                if (MODE == 2) {
                    float2 a2 = *reinterpret_cast<const float2*>(aux + (size_t)r * N + gc);
                    v0 *= a2.x; v1 *= a2.y;
                }
                if (MODE == 3) {
                    atomicAdd(C0 + (size_t)r * N + gc,     v0);
                    atomicAdd(C0 + (size_t)r * N + gc + 1, v1);
                } else {
                    float2 o; o.x = v0; o.y = v1;
                    *reinterpret_cast<float2*>(C0 + (size_t)r * N + gc) = o;
                }
            }
        }
    }
}

// ---------------- softplus -> A_bar -----------------------------------------
__global__ __launch_bounds__(256)
void softplus_kernel(const float* __restrict__ A_log)
{
    int m = blockIdx.x * 256 + threadIdx.x;
    float v = g_dsum[m];
    float sp = (v > 20.0f) ? v : log1pf(expf(v));
    g_a[m] = expf(-expf(A_log[0]) * sp);
}

// ---------------- parallel scan: 3 passes -----------------------------------
__global__ __launch_bounds__(128)
void prod_kernel()
{
    float v = g_a[blockIdx.x * 128 + threadIdx.x];
#pragma unroll
    for (int o = 16; o; o >>= 1) v *= __shfl_xor_sync(0xFFFFFFFFu, v, o);
    __shared__ float red[4];
    if ((threadIdx.x & 31) == 0) red[threadIdx.x >> 5] = v;
    __syncthreads();
    if (threadIdx.x == 0)
        g_prodA[blockIdx.x] = red[0] * red[1] * red[2] * red[3];
}

__global__ __launch_bounds__(256)
void scanA_kernel()
{
    int b = blockIdx.x >> 4, c = blockIdx.x & 15;
    int d = blockIdx.y * 256 + threadIdx.x;
    int s0 = c * CHLEN;
    float h = 0.0f;
    size_t base = ((size_t)b * SEQ + s0) * DINNER + d;
    int arow = b * SEQ + s0;
#pragma unroll 4
    for (int i = 0; i < CHLEN; i++)
        h = fmaf(g_a[arow + i], h, g_bx[base + (size_t)i * DINNER]);
    g_hend[(size_t)(b * NCH + c) * DINNER + d] = h;
}

__global__ __launch_bounds__(256)
void scanB_kernel()
{
    int b = blockIdx.x >> 3;
    int d = (blockIdx.x & 7) * 256 + threadIdx.x;
    float carry = 0.0f;
#pragma unroll
    for (int c = 0; c < NCH; c++) {
        size_t idx = (size_t)(b * NCH + c) * DINNER + d;
        g_carry[idx] = carry;
        carry = g_hend[idx] + g_prodA[b * NCH + c] * carry;
    }
}

// pass C: re-scan + fused y = (C*h + D*xi)*silu(z), rounded to tf32 for gemm_out
__global__ __launch_bounds__(256)
void scanC_kernel(const float* __restrict__ D)
{
    int b = blockIdx.x >> 4, c = blockIdx.x & 15;
    int d = blockIdx.y * 256 + threadIdx.x;
    int s0 = c * CHLEN;
    float Dd = D[d];
    float h = g_carry[(size_t)(b * NCH + c) * DINNER + d];
    size_t base = ((size_t)b * SEQ + s0) * DINNER + d;
    int arow = b * SEQ + s0;
#pragma unroll 4
    for (int i = 0; i < CHLEN; i++) {
        size_t idx = base + (size_t)i * DINNER;
        float xi = g_xi[idx];
        h = fmaf(g_a[arow + i], h, g_bx[idx]);
        float y = fmaf(g_Cm[idx], h, Dd * xi);
        g_y[idx] = tf32r(y * g_sz[idx]);
    }
}

// ---------------- launch ----------------------------------------------------
extern "C" void kernel_launch(void* const* d_in, const int* in_sizes, int n_in,
                              void* d_out, int out_size)
{
    const float* x     = (const float*)d_in[0];
    const float* W_in  = (const float*)d_in[1];
    const float* W_xp  = (const float*)d_in[2];
    const float* W_B   = (const float*)d_in[3];
    const float* W_C   = (const float*)d_in[4];
    const float* W_out = (const float*)d_in[5];
    const float* Dvec  = (const float*)d_in[6];
    const float* A_log = (const float*)d_in[7];
    float* out = (float*)d_out;

    float *p_xi, *p_sz, *p_bx, *p_Cm, *p_y, *p_pBC, *p_dsum, *p_xr;
    float *p_Wr, *p_Wor, *p_Wxh, *p_Wxl, *p_WBh, *p_WBl, *p_WCh, *p_WCl;
    cudaGetSymbolAddress((void**)&p_xi,   g_xi);
    cudaGetSymbolAddress((void**)&p_sz,   g_sz);
    cudaGetSymbolAddress((void**)&p_bx,   g_bx);
    cudaGetSymbolAddress((void**)&p_Cm,   g_Cm);
    cudaGetSymbolAddress((void**)&p_y,    g_y);
    cudaGetSymbolAddress((void**)&p_pBC,  g_pBC);
    cudaGetSymbolAddress((void**)&p_dsum, g_dsum);
    cudaGetSymbolAddress((void**)&p_xr,   g_xr);
    cudaGetSymbolAddress((void**)&p_Wr,   g_Wr);
    cudaGetSymbolAddress((void**)&p_Wor,  g_Wor);
    cudaGetSymbolAddress((void**)&p_Wxh,  g_Wxh);
    cudaGetSymbolAddress((void**)&p_Wxl,  g_Wxl);
    cudaGetSymbolAddress((void**)&p_WBh,  g_WBh);
    cudaGetSymbolAddress((void**)&p_WBl,  g_WBl);
    cudaGetSymbolAddress((void**)&p_WCh,  g_WCh);
    cudaGetSymbolAddress((void**)&p_WCl,  g_WCl);

    cudaFuncSetAttribute(gemm_cp<0>, cudaFuncAttributeMaxDynamicSharedMemorySize, GEMM_SMEM);
    cudaFuncSetAttribute(gemm_cp<1>, cudaFuncAttributeMaxDynamicSharedMemorySize, GEMM_SMEM);
    cudaFuncSetAttribute(gemm_pp<0>, cudaFuncAttributeMaxDynamicSharedMemorySize, PP_SMEM);
    cudaFuncSetAttribute(gemm_pp<2>, cudaFuncAttributeMaxDynamicSharedMemorySize, PP_SMEM);
    cudaFuncSetAttribute(gemm_pp<3>, cudaFuncAttributeMaxDynamicSharedMemorySize, PP_SMEM);

    // 0) weight/input prep + zero accumulators
    round_kernel<<<MROWS * DMODEL / 1024, 256>>>(x, p_xr, MROWS * DMODEL / 4);
    round_kernel<<<DMODEL * 2 * DINNER / 1024, 256>>>(W_in,  p_Wr,  DMODEL * 2 * DINNER / 4);
    round_kernel<<<DINNER * DMODEL / 1024, 256>>>(W_out, p_Wor, DINNER * DMODEL / 4);
    split_kernel<<<DSTATE * DINNER / 256, 256>>>(W_B, p_WBh, p_WBl, DSTATE * DINNER);
    split_kernel<<<DSTATE * DINNER / 256, 256>>>(W_C, p_WCh, p_WCl, DSTATE * DINNER);
    splitxp_kernel<<<DINNER * 128 / 256, 256>>>(W_xp);
    cudaMemsetAsync(p_pBC,  0, (size_t)MROWS * 128 * sizeof(float), 0);
    cudaMemsetAsync(p_dsum, 0, (size_t)MROWS * sizeof(float), 0);

    // 1) xz = x @ W_in, fused split -> xi, silu(z), fused delta dot -> g_dsum
    gemm_cp<1><<<dim3(32, 64), 256, GEMM_SMEM>>>(
        p_xr, DMODEL, p_Wr, 2 * DINNER, p_xi, p_sz, W_xp, 2 * DINNER, DMODEL);

    // 2) softplus -> A_bar
    softplus_kernel<<<MROWS / 256, 256>>>(A_log);

    // 3) [B_raw|C_raw] = xi @ W_xp[:,1:129]  (split-K x8, 3xtf32 prebuilt)
    gemm_pp<3><<<dim3(1, 64, 8), 256, PP_SMEM>>>(
        p_xi, DINNER, p_Wxh, p_Wxl, 128, p_pBC, nullptr, 128, DINNER / 8);

    // 4) bx = (B_raw @ W_B) * xi    (3xtf32 prebuilt)
    gemm_pp<2><<<dim3(16, 64), 256, PP_SMEM>>>(
        p_pBC, 128, p_WBh, p_WBl, DINNER, p_bx, p_xi, DINNER, DSTATE);

    // 5) Cm = C_raw @ W_C           (3xtf32 prebuilt)
    gemm_pp<0><<<dim3(16, 64), 256, PP_SMEM>>>(
        p_pBC + 64, 128, p_WCh, p_WCl, DINNER, p_Cm, nullptr, DINNER, DSTATE);

    // 6) parallel scan
    prod_kernel<<<BATCH * NCH, 128>>>();
    scanA_kernel<<<dim3(BATCH * NCH, DINNER / 256), 256>>>();
    scanB_kernel<<<BATCH * (DINNER / 256), 256>>>();
    scanC_kernel<<<dim3(BATCH * NCH, DINNER / 256), 256>>>(Dvec);

    // 7) out = y @ W_out
    gemm_cp<0><<<dim3(8, 64), 256, GEMM_SMEM>>>(
        p_y, DINNER, p_Wor, DMODEL, out, nullptr, nullptr, DMODEL, DINNER);
}